// round 2
// baseline (speedup 1.0000x reference)
#include <cuda_runtime.h>

#define T_STEPS 100
#define BATCH   2048
#define NH      128
#define NORD    6
#define NSP     512

// Scratch (device globals — no allocations allowed)
__device__ float g_H[(size_t)T_STEPS * BATCH * NH];   // 100 MiB: h outputs [T,B,128]
__device__ float g_h0[BATCH * NH];
__device__ float g_m0[BATCH * NORD];
__device__ float g_Wc[NSP * NH];                      // combined W_ssp @ W_lin
__device__ float g_bc[NSP];                           // combined bias

typedef unsigned long long ull;

__device__ __forceinline__ void ffma2(ull &d, ull a, ull b) {
    asm("fma.rn.f32x2 %0, %1, %2, %0;" : "+l"(d) : "l"(a), "l"(b));
}
__device__ __forceinline__ float sum2(ull a) {
    float lo, hi;
    asm("mov.b64 {%0,%1}, %2;" : "=f"(lo), "=f"(hi) : "l"(a));
    return lo + hi;
}

// ---------------------------------------------------------------------------
// Kernel 1: initial states  m0 = ssp @ w_c^T,  h0 = ssp @ w_h^T
// 128 CTAs x 128 threads, 16 batch rows per CTA.
// ---------------------------------------------------------------------------
__global__ void k_setup(const float* __restrict__ ssp,
                        const float* __restrict__ w_c,
                        const float* __restrict__ w_h) {
    __shared__ float s[16 * 512];
    const int tid = threadIdx.x;
    const int b0 = blockIdx.x * 16;
    for (int i = tid; i < 16 * 512; i += 128) s[i] = ssp[(size_t)b0 * 512 + i];
    __syncthreads();

    // h0: thread j streams w_h row j, 16 row-accumulators
    {
        float acc[16];
        #pragma unroll
        for (int r = 0; r < 16; r++) acc[r] = 0.f;
        const float* wr = w_h + tid * 512;
        for (int k = 0; k < 512; k += 4) {
            const float4 w4 = *(const float4*)(wr + k);
            #pragma unroll
            for (int r = 0; r < 16; r++) {
                const float4 x4 = *(const float4*)(s + r * 512 + k);
                acc[r] += x4.x * w4.x + x4.y * w4.y + x4.z * w4.z + x4.w * w4.w;
            }
        }
        #pragma unroll
        for (int r = 0; r < 16; r++) g_h0[(size_t)(b0 + r) * NH + tid] = acc[r];
    }
    // m0: threads 0..95, (o, r) = (t/16, t%16)
    if (tid < 96) {
        const int o = tid >> 4, r = tid & 15;
        const float* wc = w_c + o * 512;
        float a = 0.f;
        for (int k = 0; k < 512; k++) a += s[r * 512 + k] * wc[k];
        g_m0[(size_t)(b0 + r) * NORD + o] = a;
    }
}

// ---------------------------------------------------------------------------
// Kernel 2: combined projection weights  Wc = W_ssp @ W_lin, bc = W_ssp@b_lin + b_ssp
// 128 CTAs x 128 threads, 4 output rows (i) per CTA.
// ---------------------------------------------------------------------------
__global__ void k_combine(const float* __restrict__ W_lin,
                          const float* __restrict__ b_lin,
                          const float* __restrict__ W_ssp,
                          const float* __restrict__ b_ssp) {
    __shared__ float s[4 * 512];
    const int tid = threadIdx.x;
    const int i0 = blockIdx.x * 4;
    for (int i = tid; i < 4 * 512; i += 128) s[i] = W_ssp[(size_t)i0 * 512 + i];
    __syncthreads();

    float acc[4] = {0.f, 0.f, 0.f, 0.f};
    for (int j = 0; j < 512; j++) {
        const float wl = W_lin[j * 128 + tid];
        #pragma unroll
        for (int r = 0; r < 4; r++) acc[r] += s[r * 512 + j] * wl;
    }
    #pragma unroll
    for (int r = 0; r < 4; r++) g_Wc[(size_t)(i0 + r) * NH + tid] = acc[r];

    if (tid < 4) {
        float a = b_ssp[i0 + tid];
        for (int j = 0; j < 512; j++) a += s[tid * 512 + j] * b_lin[j];
        g_bc[i0 + tid] = a;
    }
}

// ---------------------------------------------------------------------------
// Kernel 3: recurrence. 128 CTAs x 128 threads (4 warps), 16 rows/CTA,
// each warp owns 4 batch rows for all 100 steps. HK held in SMEM in a
// k-pair-interleaved layout for packed f32x2 FMA.
// SMEM floats: wp 16384 | h 2048 | m 128 | mkT 768 | ikT 256 | he 128 | misc 64
// ---------------------------------------------------------------------------
__global__ void __launch_bounds__(128) k_recur(
    const float* __restrict__ vel,
    const float* __restrict__ ie_g, const float* __restrict__ he_g,
    const float* __restrict__ me_g, const float* __restrict__ ik_g,
    const float* __restrict__ hk_g, const float* __restrict__ mk_g,
    const float* __restrict__ AT_g, const float* __restrict__ BT_g) {
    extern __shared__ float sm[];
    float* s_wp = sm;            // [k4][j][4]: hk[j][4*k4+p]
    float* s_h  = sm + 16384;    // [16][128]
    float* s_m  = sm + 18432;    // [16][8]
    float* s_mk = sm + 18560;    // [o][j]  (6 x 128)
    float* s_ik = sm + 19328;    // [i][j]  (2 x 128)
    float* s_he = sm + 19584;    // [128]
    float* s_x  = sm + 19712;    // AT[36] BT[6] me[6] ie[2]

    const int tid = threadIdx.x;
    const int b0 = blockIdx.x * 16;

    for (int idx = tid; idx < 16384; idx += 128) {
        const int j = idx >> 7, k = idx & 127;
        s_wp[(((k >> 2) << 7) + j) * 4 + (k & 3)] = hk_g[idx];
    }
    for (int idx = tid; idx < 768; idx += 128) {
        const int o = idx >> 7, j = idx & 127;
        s_mk[idx] = mk_g[j * 6 + o];
    }
    for (int idx = tid; idx < 256; idx += 128) {
        const int i = idx >> 7, j = idx & 127;
        s_ik[idx] = ik_g[j * 2 + i];
    }
    if (tid < 128) s_he[tid] = he_g[tid];
    if (tid < 36) s_x[tid] = AT_g[tid];
    if (tid < 6) { s_x[36 + tid] = BT_g[tid]; s_x[42 + tid] = me_g[tid]; }
    if (tid < 2) s_x[48 + tid] = ie_g[tid];
    for (int idx = tid; idx < 16 * 128; idx += 128) s_h[idx] = g_h0[(size_t)b0 * NH + idx];
    for (int idx = tid; idx < 16 * 6; idx += 128)
        s_m[(idx / 6) * 8 + (idx % 6)] = g_m0[(size_t)b0 * NORD + idx];
    __syncthreads();

    const int lane = tid & 31;
    const int rbase = (tid >> 5) * 4;   // 4 rows per warp
    const float ie0 = s_x[48], ie1 = s_x[49];

    #pragma unroll 1
    for (int t = 0; t < T_STEPS; t++) {
        const float* vptr = vel + ((size_t)t * BATCH + b0 + rbase) * 2;
        float v0[4], v1[4], u[4];
        #pragma unroll
        for (int r = 0; r < 4; r++) { v0[r] = vptr[r * 2]; v1[r] = vptr[r * 2 + 1]; }

        // u = v.ie + h.he + m.me   (old h, old m)
        #pragma unroll
        for (int r = 0; r < 4; r++) {
            const float* hr = s_h + (rbase + r) * 128;
            float up = 0.f;
            #pragma unroll
            for (int q = 0; q < 4; q++) up += s_he[lane + 32 * q] * hr[lane + 32 * q];
            #pragma unroll
            for (int o = 16; o > 0; o >>= 1) up += __shfl_xor_sync(0xffffffffu, up, o);
            const float* mr = s_m + (rbase + r) * 8;
            up += ie0 * v0[r] + ie1 * v1[r];
            #pragma unroll
            for (int o = 0; o < 6; o++) up += s_x[42 + o] * mr[o];
            u[r] = up;
        }

        // m' = m + AT@m + BT*u   (lanes 0..5)
        float mnew[4];
        if (lane < 6) {
            #pragma unroll
            for (int r = 0; r < 4; r++) {
                const float* mr = s_m + (rbase + r) * 8;
                float a = mr[lane] + s_x[36 + lane] * u[r];
                #pragma unroll
                for (int k = 0; k < 6; k++) a += s_x[lane * 6 + k] * mr[k];
                mnew[r] = a;
            }
        }
        __syncwarp();
        if (lane < 6) {
            #pragma unroll
            for (int r = 0; r < 4; r++) s_m[(rbase + r) * 8 + lane] = mnew[r];
        }
        __syncwarp();

        float mn[4][6];
        #pragma unroll
        for (int r = 0; r < 4; r++)
            #pragma unroll
            for (int o = 0; o < 6; o++) mn[r][o] = s_m[(rbase + r) * 8 + o];

        // h' = tanh(HK@h + MK@m' + IK@v) : packed f32x2 matvec, 4 rows x 4 j-chunks
        ull acc[4][4];
        #pragma unroll
        for (int r = 0; r < 4; r++)
            #pragma unroll
            for (int q = 0; q < 4; q++) acc[r][q] = 0ull;

        #pragma unroll 2
        for (int k4 = 0; k4 < 32; k4++) {
            ulonglong2 hp[4];
            #pragma unroll
            for (int r = 0; r < 4; r++)
                hp[r] = *(const ulonglong2*)(s_h + (rbase + r) * 128 + k4 * 4);
            #pragma unroll
            for (int q = 0; q < 4; q++) {
                const ulonglong2 wp =
                    *(const ulonglong2*)(s_wp + ((k4 << 7) + lane + 32 * q) * 4);
                #pragma unroll
                for (int r = 0; r < 4; r++) {
                    ffma2(acc[r][q], hp[r].x, wp.x);
                    ffma2(acc[r][q], hp[r].y, wp.y);
                }
            }
        }

        float hv[4][4];
        #pragma unroll
        for (int r = 0; r < 4; r++) {
            #pragma unroll
            for (int q = 0; q < 4; q++) {
                const int j = lane + 32 * q;
                float x = sum2(acc[r][q]);
                #pragma unroll
                for (int o = 0; o < 6; o++) x += mn[r][o] * s_mk[o * 128 + j];
                x += v0[r] * s_ik[j] + v1[r] * s_ik[128 + j];
                const float e = __expf(2.f * x);          // tanh = 1 - 2/(e^{2x}+1)
                hv[r][q] = 1.f - __fdividef(2.f, e + 1.f);
            }
        }
        __syncwarp();
        #pragma unroll
        for (int r = 0; r < 4; r++) {
            float* hr = s_h + (rbase + r) * 128;
            float* go = g_H + ((size_t)t * BATCH + b0 + rbase + r) * NH;
            #pragma unroll
            for (int q = 0; q < 4; q++) {
                const int j = lane + 32 * q;
                hr[j] = hv[r][q];
                go[j] = hv[r][q];
            }
        }
        __syncwarp();
    }
}

// ---------------------------------------------------------------------------
// Kernel 4: projection  Y = H @ Wc^T + bc  (M=204800, N=512, K=128)
// 128x128 tile per CTA, 256 threads, 8x8 per thread, packed f32x2 FMA.
// ---------------------------------------------------------------------------
__global__ void __launch_bounds__(256) k_proj(float* __restrict__ out) {
    extern __shared__ float sm[];
    float* Xs = sm;            // [k4][row][4]
    float* Ws = sm + 16384;    // [k4][col][4]
    const int tid = threadIdx.x;
    const size_t row0 = (size_t)blockIdx.y * 128;
    const int col0 = blockIdx.x * 128;

    const float* Xg = g_H + row0 * NH;
    for (int idx = tid; idx < 16384; idx += 256) {
        const int r = idx >> 7, k = idx & 127;
        Xs[(((k >> 2) << 7) + r) * 4 + (k & 3)] = Xg[idx];
    }
    const float* Wg = g_Wc + (size_t)col0 * NH;
    for (int idx = tid; idx < 16384; idx += 256) {
        const int c = idx >> 7, k = idx & 127;
        Ws[(((k >> 2) << 7) + c) * 4 + (k & 3)] = Wg[idx];
    }
    __syncthreads();

    const int tx = tid & 15, ty = tid >> 4;
    ull acc[8][8];
    #pragma unroll
    for (int i = 0; i < 8; i++)
        #pragma unroll
        for (int j = 0; j < 8; j++) acc[i][j] = 0ull;

    for (int k4 = 0; k4 < 32; k4++) {
        ulonglong2 a[8];
        #pragma unroll
        for (int rr = 0; rr < 8; rr++)
            a[rr] = *(const ulonglong2*)(Xs + ((k4 << 7) + ty + 16 * rr) * 4);
        #pragma unroll
        for (int cc = 0; cc < 8; cc++) {
            const ulonglong2 b = *(const ulonglong2*)(Ws + ((k4 << 7) + tx + 16 * cc) * 4);
            #pragma unroll
            for (int rr = 0; rr < 8; rr++) {
                ffma2(acc[rr][cc], a[rr].x, b.x);
                ffma2(acc[rr][cc], a[rr].y, b.y);
            }
        }
    }

    #pragma unroll
    for (int cc = 0; cc < 8; cc++) {
        const int col = col0 + tx + 16 * cc;
        const float bias = g_bc[col];
        #pragma unroll
        for (int rr = 0; rr < 8; rr++) {
            const size_t row = row0 + ty + 16 * rr;
            out[row * NSP + col] = sum2(acc[rr][cc]) + bias;
        }
    }
}

// ---------------------------------------------------------------------------
extern "C" void kernel_launch(void* const* d_in, const int* in_sizes, int n_in,
                              void* d_out, int out_size) {
    const float* vel   = (const float*)d_in[0];
    const float* ssp0  = (const float*)d_in[1];
    const float* ie    = (const float*)d_in[2];
    const float* he    = (const float*)d_in[3];
    const float* me    = (const float*)d_in[4];
    const float* ik    = (const float*)d_in[5];
    const float* hk    = (const float*)d_in[6];
    const float* mk    = (const float*)d_in[7];
    const float* AT    = (const float*)d_in[8];
    const float* BT    = (const float*)d_in[9];
    const float* w_c   = (const float*)d_in[10];
    const float* w_h   = (const float*)d_in[11];
    const float* W_lin = (const float*)d_in[12];
    const float* b_lin = (const float*)d_in[13];
    const float* W_ssp = (const float*)d_in[14];
    const float* b_ssp = (const float*)d_in[15];
    float* out = (float*)d_out;

    cudaFuncSetAttribute(k_recur, cudaFuncAttributeMaxDynamicSharedMemorySize, 80 * 1024);
    cudaFuncSetAttribute(k_proj,  cudaFuncAttributeMaxDynamicSharedMemorySize, 132 * 1024);

    k_setup<<<128, 128>>>(ssp0, w_c, w_h);
    k_combine<<<128, 128>>>(W_lin, b_lin, W_ssp, b_ssp);
    k_recur<<<128, 128, 79104>>>(vel, ie, he, me, ik, hk, mk, AT, BT);
    dim3 g(4, 1600);
    k_proj<<<g, 256, 131072>>>(out);
}

// round 4
// speedup vs baseline: 1.4015x; 1.4015x over previous
#include <cuda_runtime.h>
#include <cuda_bf16.h>

#define T_STEPS 100
#define BATCH   2048
#define NH      128
#define NORD    6
#define NSP     512

typedef unsigned long long ull;
typedef unsigned int u32;

// Scratch (device globals — no allocations allowed)
__device__ __align__(16) __nv_bfloat162 g_Hp[(size_t)T_STEPS * BATCH * NH]; // (hi,lo) per h elem
__device__ __align__(16) float g_h0[BATCH * NH];
__device__ __align__(16) float g_m0[BATCH * NORD];
__device__ __align__(16) __nv_bfloat162 g_Wcp[NSP * NH];                    // combined W, (hi,lo)
__device__ __align__(16) float g_bc[NSP];

__device__ __forceinline__ void ffma2(ull &d, ull a, ull b) {
    asm("fma.rn.f32x2 %0, %1, %2, %0;" : "+l"(d) : "l"(a), "l"(b));
}
__device__ __forceinline__ float sum2(ull a) {
    float lo, hi;
    asm("mov.b64 {%0,%1}, %2;" : "=f"(lo), "=f"(hi) : "l"(a));
    return lo + hi;
}
__device__ __forceinline__ u32 smem_u32(const void* p) {
    u32 a;
    asm("{ .reg .u64 t; cvta.to.shared.u64 t, %1; cvt.u32.u64 %0, t; }" : "=r"(a) : "l"(p));
    return a;
}
__device__ __forceinline__ __nv_bfloat162 split_bf(float x) {
    __nv_bfloat16 hi = __float2bfloat16(x);
    __nv_bfloat16 lo = __float2bfloat16(x - __bfloat162float(hi));
    __nv_bfloat162 r; r.x = hi; r.y = lo; return r;
}

// ---------------------------------------------------------------------------
// Kernel 1: initial states  m0 = ssp @ w_c^T,  h0 = ssp @ w_h^T
// ---------------------------------------------------------------------------
__global__ void k_setup(const float* __restrict__ ssp,
                        const float* __restrict__ w_c,
                        const float* __restrict__ w_h) {
    __shared__ float s[16 * 512];
    const int tid = threadIdx.x;
    const int b0 = blockIdx.x * 16;
    for (int i = tid; i < 16 * 512; i += 128) s[i] = ssp[(size_t)b0 * 512 + i];
    __syncthreads();
    {
        float acc[16];
        #pragma unroll
        for (int r = 0; r < 16; r++) acc[r] = 0.f;
        const float* wr = w_h + tid * 512;
        for (int k = 0; k < 512; k += 4) {
            const float4 w4 = *(const float4*)(wr + k);
            #pragma unroll
            for (int r = 0; r < 16; r++) {
                const float4 x4 = *(const float4*)(s + r * 512 + k);
                acc[r] += x4.x * w4.x + x4.y * w4.y + x4.z * w4.z + x4.w * w4.w;
            }
        }
        #pragma unroll
        for (int r = 0; r < 16; r++) g_h0[(size_t)(b0 + r) * NH + tid] = acc[r];
    }
    if (tid < 96) {
        const int o = tid >> 4, r = tid & 15;
        const float* wc = w_c + o * 512;
        float a = 0.f;
        for (int k = 0; k < 512; k++) a += s[r * 512 + k] * wc[k];
        g_m0[(size_t)(b0 + r) * NORD + o] = a;
    }
}

// ---------------------------------------------------------------------------
// Kernel 2: combined weights  Wc = W_ssp @ W_lin (stored split-bf16), bc
// ---------------------------------------------------------------------------
__global__ void k_combine(const float* __restrict__ W_lin,
                          const float* __restrict__ b_lin,
                          const float* __restrict__ W_ssp,
                          const float* __restrict__ b_ssp) {
    __shared__ float s[4 * 512];
    const int tid = threadIdx.x;
    const int i0 = blockIdx.x * 4;
    for (int i = tid; i < 4 * 512; i += 128) s[i] = W_ssp[(size_t)i0 * 512 + i];
    __syncthreads();

    float acc[4] = {0.f, 0.f, 0.f, 0.f};
    for (int j = 0; j < 512; j++) {
        const float wl = W_lin[j * 128 + tid];
        #pragma unroll
        for (int r = 0; r < 4; r++) acc[r] += s[r * 512 + j] * wl;
    }
    #pragma unroll
    for (int r = 0; r < 4; r++) g_Wcp[(size_t)(i0 + r) * NH + tid] = split_bf(acc[r]);

    if (tid < 4) {
        float a = b_ssp[i0 + tid];
        for (int j = 0; j < 512; j++) a += s[tid * 512 + j] * b_lin[j];
        g_bc[i0 + tid] = a;
    }
}

// ---------------------------------------------------------------------------
// Kernel 3: recurrence (fp32 state in SMEM, split-bf16 output to g_Hp)
// ---------------------------------------------------------------------------
__global__ void __launch_bounds__(128) k_recur(
    const float* __restrict__ vel,
    const float* __restrict__ ie_g, const float* __restrict__ he_g,
    const float* __restrict__ me_g, const float* __restrict__ ik_g,
    const float* __restrict__ hk_g, const float* __restrict__ mk_g,
    const float* __restrict__ AT_g, const float* __restrict__ BT_g) {
    extern __shared__ float sm[];
    float* s_wp = sm;            // [k4][j][4]
    float* s_h  = sm + 16384;    // [16][128]
    float* s_m  = sm + 18432;    // [16][8]
    float* s_mk = sm + 18560;    // [o][j]
    float* s_ik = sm + 19328;    // [i][j]
    float* s_he = sm + 19584;
    float* s_x  = sm + 19712;    // AT[36] BT[6] me[6] ie[2]

    const int tid = threadIdx.x;
    const int b0 = blockIdx.x * 16;

    for (int idx = tid; idx < 16384; idx += 128) {
        const int j = idx >> 7, k = idx & 127;
        s_wp[(((k >> 2) << 7) + j) * 4 + (k & 3)] = hk_g[idx];
    }
    for (int idx = tid; idx < 768; idx += 128) {
        const int o = idx >> 7, j = idx & 127;
        s_mk[idx] = mk_g[j * 6 + o];
    }
    for (int idx = tid; idx < 256; idx += 128) {
        const int i = idx >> 7, j = idx & 127;
        s_ik[idx] = ik_g[j * 2 + i];
    }
    if (tid < 128) s_he[tid] = he_g[tid];
    if (tid < 36) s_x[tid] = AT_g[tid];
    if (tid < 6) { s_x[36 + tid] = BT_g[tid]; s_x[42 + tid] = me_g[tid]; }
    if (tid < 2) s_x[48 + tid] = ie_g[tid];
    for (int idx = tid; idx < 16 * 128; idx += 128) s_h[idx] = g_h0[(size_t)b0 * NH + idx];
    for (int idx = tid; idx < 16 * 6; idx += 128)
        s_m[(idx / 6) * 8 + (idx % 6)] = g_m0[(size_t)b0 * NORD + idx];
    __syncthreads();

    const int lane = tid & 31;
    const int rbase = (tid >> 5) * 4;
    const float ie0 = s_x[48], ie1 = s_x[49];

    #pragma unroll 1
    for (int t = 0; t < T_STEPS; t++) {
        const float* vptr = vel + ((size_t)t * BATCH + b0 + rbase) * 2;
        float v0[4], v1[4], u[4];
        #pragma unroll
        for (int r = 0; r < 4; r++) { v0[r] = vptr[r * 2]; v1[r] = vptr[r * 2 + 1]; }

        #pragma unroll
        for (int r = 0; r < 4; r++) {
            const float* hr = s_h + (rbase + r) * 128;
            float up = 0.f;
            #pragma unroll
            for (int q = 0; q < 4; q++) up += s_he[lane + 32 * q] * hr[lane + 32 * q];
            #pragma unroll
            for (int o = 16; o > 0; o >>= 1) up += __shfl_xor_sync(0xffffffffu, up, o);
            const float* mr = s_m + (rbase + r) * 8;
            up += ie0 * v0[r] + ie1 * v1[r];
            #pragma unroll
            for (int o = 0; o < 6; o++) up += s_x[42 + o] * mr[o];
            u[r] = up;
        }

        float mnew[4];
        if (lane < 6) {
            #pragma unroll
            for (int r = 0; r < 4; r++) {
                const float* mr = s_m + (rbase + r) * 8;
                float a = mr[lane] + s_x[36 + lane] * u[r];
                #pragma unroll
                for (int k = 0; k < 6; k++) a += s_x[lane * 6 + k] * mr[k];
                mnew[r] = a;
            }
        }
        __syncwarp();
        if (lane < 6) {
            #pragma unroll
            for (int r = 0; r < 4; r++) s_m[(rbase + r) * 8 + lane] = mnew[r];
        }
        __syncwarp();

        float mn[4][6];
        #pragma unroll
        for (int r = 0; r < 4; r++)
            #pragma unroll
            for (int o = 0; o < 6; o++) mn[r][o] = s_m[(rbase + r) * 8 + o];

        ull acc[4][4];
        #pragma unroll
        for (int r = 0; r < 4; r++)
            #pragma unroll
            for (int q = 0; q < 4; q++) acc[r][q] = 0ull;

        #pragma unroll 2
        for (int k4 = 0; k4 < 32; k4++) {
            ulonglong2 hp[4];
            #pragma unroll
            for (int r = 0; r < 4; r++)
                hp[r] = *(const ulonglong2*)(s_h + (rbase + r) * 128 + k4 * 4);
            #pragma unroll
            for (int q = 0; q < 4; q++) {
                const ulonglong2 wp =
                    *(const ulonglong2*)(s_wp + ((k4 << 7) + lane + 32 * q) * 4);
                #pragma unroll
                for (int r = 0; r < 4; r++) {
                    ffma2(acc[r][q], hp[r].x, wp.x);
                    ffma2(acc[r][q], hp[r].y, wp.y);
                }
            }
        }

        float hv[4][4];
        #pragma unroll
        for (int r = 0; r < 4; r++) {
            #pragma unroll
            for (int q = 0; q < 4; q++) {
                const int j = lane + 32 * q;
                float x = sum2(acc[r][q]);
                #pragma unroll
                for (int o = 0; o < 6; o++) x += mn[r][o] * s_mk[o * 128 + j];
                x += v0[r] * s_ik[j] + v1[r] * s_ik[128 + j];
                const float e = __expf(2.f * x);
                hv[r][q] = 1.f - __fdividef(2.f, e + 1.f);
            }
        }
        __syncwarp();
        #pragma unroll
        for (int r = 0; r < 4; r++) {
            float* hr = s_h + (rbase + r) * 128;
            __nv_bfloat162* go = g_Hp + ((size_t)t * BATCH + b0 + rbase + r) * NH;
            #pragma unroll
            for (int q = 0; q < 4; q++) {
                const int j = lane + 32 * q;
                hr[j] = hv[r][q];
                go[j] = split_bf(hv[r][q]);
            }
        }
        __syncwarp();
    }
}

// ---------------------------------------------------------------------------
// Kernel 4: projection via mma.sync (HMMA) split-bf16, 3 passes in-register.
// C[204800,512] = Hsplit @ Wcsplit^T + bc. CTA tile 128x128, K=128, 8 warps.
// SMEM: A_hi 32K | A_lo 32K | B_hi 32K | B_lo 32K = 128KB.
// Swizzle: byte = row*256 + ((chunk16 ^ (row&7))<<4) + sub8  (conflict-free
// for per-row stores and for ldmatrix 8-lane phases).
// ---------------------------------------------------------------------------
#define PJ_A_HI 0
#define PJ_A_LO 32768
#define PJ_B_HI 65536
#define PJ_B_LO 98304
#define PJ_SMEM 131072

__device__ __forceinline__ void ldsm4(u32* r, u32 addr) {
    asm volatile("ldmatrix.sync.aligned.m8n8.x4.shared.b16 {%0,%1,%2,%3}, [%4];"
        : "=r"(r[0]), "=r"(r[1]), "=r"(r[2]), "=r"(r[3]) : "r"(addr));
}
__device__ __forceinline__ void mma16816(float* c, const u32* a, const u32* b) {
    asm volatile(
        "mma.sync.aligned.m16n8k16.row.col.f32.bf16.bf16.f32 "
        "{%0,%1,%2,%3}, {%4,%5,%6,%7}, {%8,%9}, {%0,%1,%2,%3};"
        : "+f"(c[0]), "+f"(c[1]), "+f"(c[2]), "+f"(c[3])
        : "r"(a[0]), "r"(a[1]), "r"(a[2]), "r"(a[3]), "r"(b[0]), "r"(b[1]));
}

__global__ void __launch_bounds__(256) k_proj(float* __restrict__ out) {
    extern __shared__ char smc[];
    const u32 sb = smem_u32(smc);
    const int tid = threadIdx.x;
    const int w = tid >> 5, lane = tid & 31;
    const int col0 = blockIdx.x * 128;
    const int row0 = blockIdx.y * 128;

    // Stage + split A tile (128 rows x 128 (hi,lo) pairs)
    {
        const uint4* Ag = (const uint4*)(g_Hp + (size_t)row0 * NH);
        for (int idx = tid; idx < 128 * 32; idx += 256) {
            const int row = idx >> 5, c4 = idx & 31;
            const uint4 v = Ag[idx];
            uint2 hi, lo;
            hi.x = (v.x & 0xffffu) | (v.y << 16);
            hi.y = (v.z & 0xffffu) | (v.w << 16);
            lo.x = (v.x >> 16) | (v.y & 0xffff0000u);
            lo.y = (v.z >> 16) | (v.w & 0xffff0000u);
            const u32 o = (u32)row * 256 + ((u32)(((c4 >> 1) ^ (row & 7)) << 4)) + (c4 & 1) * 8;
            *(uint2*)(smc + PJ_A_HI + o) = hi;
            *(uint2*)(smc + PJ_A_LO + o) = lo;
        }
    }
    // Stage + split B tile (128 cols of Wc)
    {
        const uint4* Bg = (const uint4*)(g_Wcp + (size_t)col0 * NH);
        for (int idx = tid; idx < 128 * 32; idx += 256) {
            const int row = idx >> 5, c4 = idx & 31;
            const uint4 v = Bg[idx];
            uint2 hi, lo;
            hi.x = (v.x & 0xffffu) | (v.y << 16);
            hi.y = (v.z & 0xffffu) | (v.w << 16);
            lo.x = (v.x >> 16) | (v.y & 0xffff0000u);
            lo.y = (v.z >> 16) | (v.w & 0xffff0000u);
            const u32 o = (u32)row * 256 + ((u32)(((c4 >> 1) ^ (row & 7)) << 4)) + (c4 & 1) * 8;
            *(uint2*)(smc + PJ_B_HI + o) = hi;
            *(uint2*)(smc + PJ_B_LO + o) = lo;
        }
    }
    __syncthreads();

    // Warp grid: 2 (m) x 4 (n). Warp tile 64 x 32 = 4 mtiles x 4 ntiles.
    const int wm = w & 1, wn = w >> 1;
    const int mbase = wm * 64, nbase = wn * 32;

    float acc[4][4][4];
    #pragma unroll
    for (int mt = 0; mt < 4; mt++)
        #pragma unroll
        for (int nt = 0; nt < 4; nt++)
            #pragma unroll
            for (int i = 0; i < 4; i++) acc[mt][nt][i] = 0.f;

    // ldmatrix lane roles:
    // A x4: mats [m0-7,kL][m8-15,kL][m0-7,kH][m8-15,kH]
    const int arow_l = lane & 15, asel = lane >> 4;
    // B x4: mats [n0-7,kL][n0-7,kH][n8-15,kL][n8-15,kH]
    const int brow_l = ((lane >> 4) << 3) + (lane & 7), bsel = (lane >> 3) & 1;

    #pragma unroll
    for (int kk = 0; kk < 8; kk++) {
        u32 ahi[4][4], alo[4][4];
        #pragma unroll
        for (int mt = 0; mt < 4; mt++) {
            const int row = mbase + mt * 16 + arow_l;
            const u32 off = (u32)row * 256 + ((u32)(((2 * kk + asel) ^ (row & 7)) << 4));
            ldsm4(ahi[mt], sb + PJ_A_HI + off);
            ldsm4(alo[mt], sb + PJ_A_LO + off);
        }
        u32 bhi[2][4], blo[2][4];
        #pragma unroll
        for (int np = 0; np < 2; np++) {
            const int row = nbase + np * 16 + brow_l;
            const u32 off = (u32)row * 256 + ((u32)(((2 * kk + bsel) ^ (row & 7)) << 4));
            ldsm4(bhi[np], sb + PJ_B_HI + off);
            ldsm4(blo[np], sb + PJ_B_LO + off);
        }
        #pragma unroll
        for (int mt = 0; mt < 4; mt++) {
            #pragma unroll
            for (int nt = 0; nt < 4; nt++) {
                const u32* bh = &bhi[nt >> 1][(nt & 1) * 2];
                const u32* bl = &blo[nt >> 1][(nt & 1) * 2];
                mma16816(acc[mt][nt], ahi[mt], bh);   // hi*hi
                mma16816(acc[mt][nt], alo[mt], bh);   // lo*hi
                mma16816(acc[mt][nt], ahi[mt], bl);   // hi*lo
            }
        }
    }

    // Epilogue: C-fragment layout -> direct float2 stores + bias
    const int tq = lane >> 2, tr = lane & 3;
    #pragma unroll
    for (int nt = 0; nt < 4; nt++) {
        const int ncol = col0 + nbase + nt * 8 + tr * 2;
        const float2 bias = *(const float2*)(g_bc + ncol);
        #pragma unroll
        for (int mt = 0; mt < 4; mt++) {
            const int mrow = row0 + mbase + mt * 16 + tq;
            float2 v0, v1;
            v0.x = acc[mt][nt][0] + bias.x; v0.y = acc[mt][nt][1] + bias.y;
            v1.x = acc[mt][nt][2] + bias.x; v1.y = acc[mt][nt][3] + bias.y;
            *(float2*)(out + (size_t)mrow * NSP + ncol) = v0;
            *(float2*)(out + (size_t)(mrow + 8) * NSP + ncol) = v1;
        }
    }
}

// ---------------------------------------------------------------------------
extern "C" void kernel_launch(void* const* d_in, const int* in_sizes, int n_in,
                              void* d_out, int out_size) {
    const float* vel   = (const float*)d_in[0];
    const float* ssp0  = (const float*)d_in[1];
    const float* ie    = (const float*)d_in[2];
    const float* he    = (const float*)d_in[3];
    const float* me    = (const float*)d_in[4];
    const float* ik    = (const float*)d_in[5];
    const float* hk    = (const float*)d_in[6];
    const float* mk    = (const float*)d_in[7];
    const float* AT    = (const float*)d_in[8];
    const float* BT    = (const float*)d_in[9];
    const float* w_c   = (const float*)d_in[10];
    const float* w_h   = (const float*)d_in[11];
    const float* W_lin = (const float*)d_in[12];
    const float* b_lin = (const float*)d_in[13];
    const float* W_ssp = (const float*)d_in[14];
    const float* b_ssp = (const float*)d_in[15];
    float* out = (float*)d_out;

    cudaFuncSetAttribute(k_recur, cudaFuncAttributeMaxDynamicSharedMemorySize, 80 * 1024);
    cudaFuncSetAttribute(k_proj,  cudaFuncAttributeMaxDynamicSharedMemorySize, PJ_SMEM);

    k_setup<<<128, 128>>>(ssp0, w_c, w_h);
    k_combine<<<128, 128>>>(W_lin, b_lin, W_ssp, b_ssp);
    k_recur<<<128, 128, 79104>>>(vel, ie, he, me, ik, hk, mk, AT, BT);
    dim3 g(4, 1600);
    k_proj<<<g, 256, PJ_SMEM>>>(out);
}

// round 5
// speedup vs baseline: 2.0299x; 1.4484x over previous
#include <cuda_runtime.h>
#include <cuda_bf16.h>

#define T_STEPS 100
#define BATCH   2048
#define NH      128
#define NORD    6
#define NSP     512

typedef unsigned long long ull;
typedef unsigned int u32;

// Scratch (device globals — no allocations allowed)
__device__ __align__(16) __nv_bfloat162 g_Hp[(size_t)T_STEPS * BATCH * NH]; // (hi,lo) per h elem
__device__ __align__(16) float g_h0[BATCH * NH];
__device__ __align__(16) float g_m0[BATCH * NORD];
__device__ __align__(16) __nv_bfloat162 g_Wcp[NSP * NH];                    // combined W, (hi,lo)
__device__ __align__(16) float g_bc[NSP];

__device__ __forceinline__ void ffma2(ull &d, ull a, ull b) {
    asm("fma.rn.f32x2 %0, %1, %2, %0;" : "+l"(d) : "l"(a), "l"(b));
}
__device__ __forceinline__ float sum2(ull a) {
    float lo, hi;
    asm("mov.b64 {%0,%1}, %2;" : "=f"(lo), "=f"(hi) : "l"(a));
    return lo + hi;
}
__device__ __forceinline__ u32 smem_u32(const void* p) {
    u32 a;
    asm("{ .reg .u64 t; cvta.to.shared.u64 t, %1; cvt.u32.u64 %0, t; }" : "=r"(a) : "l"(p));
    return a;
}
__device__ __forceinline__ __nv_bfloat162 split_bf(float x) {
    __nv_bfloat16 hi = __float2bfloat16(x);
    __nv_bfloat16 lo = __float2bfloat16(x - __bfloat162float(hi));
    __nv_bfloat162 r; r.x = hi; r.y = lo; return r;
}

// ---------------------------------------------------------------------------
// Kernel 1: initial states  m0 = ssp @ w_c^T,  h0 = ssp @ w_h^T
// ---------------------------------------------------------------------------
__global__ void k_setup(const float* __restrict__ ssp,
                        const float* __restrict__ w_c,
                        const float* __restrict__ w_h) {
    __shared__ float s[16 * 512];
    const int tid = threadIdx.x;
    const int b0 = blockIdx.x * 16;
    for (int i = tid; i < 16 * 512; i += 128) s[i] = ssp[(size_t)b0 * 512 + i];
    __syncthreads();
    {
        float acc[16];
        #pragma unroll
        for (int r = 0; r < 16; r++) acc[r] = 0.f;
        const float* wr = w_h + tid * 512;
        for (int k = 0; k < 512; k += 4) {
            const float4 w4 = *(const float4*)(wr + k);
            #pragma unroll
            for (int r = 0; r < 16; r++) {
                const float4 x4 = *(const float4*)(s + r * 512 + k);
                acc[r] += x4.x * w4.x + x4.y * w4.y + x4.z * w4.z + x4.w * w4.w;
            }
        }
        #pragma unroll
        for (int r = 0; r < 16; r++) g_h0[(size_t)(b0 + r) * NH + tid] = acc[r];
    }
    if (tid < 96) {
        const int o = tid >> 4, r = tid & 15;
        const float* wc = w_c + o * 512;
        float a = 0.f;
        for (int k = 0; k < 512; k++) a += s[r * 512 + k] * wc[k];
        g_m0[(size_t)(b0 + r) * NORD + o] = a;
    }
}

// ---------------------------------------------------------------------------
// Kernel 2: combined weights  Wc = W_ssp @ W_lin (stored split-bf16), bc
// ---------------------------------------------------------------------------
__global__ void k_combine(const float* __restrict__ W_lin,
                          const float* __restrict__ b_lin,
                          const float* __restrict__ W_ssp,
                          const float* __restrict__ b_ssp) {
    __shared__ float s[4 * 512];
    const int tid = threadIdx.x;
    const int i0 = blockIdx.x * 4;
    for (int i = tid; i < 4 * 512; i += 128) s[i] = W_ssp[(size_t)i0 * 512 + i];
    __syncthreads();

    float acc[4] = {0.f, 0.f, 0.f, 0.f};
    for (int j = 0; j < 512; j++) {
        const float wl = W_lin[j * 128 + tid];
        #pragma unroll
        for (int r = 0; r < 4; r++) acc[r] += s[r * 512 + j] * wl;
    }
    #pragma unroll
    for (int r = 0; r < 4; r++) g_Wcp[(size_t)(i0 + r) * NH + tid] = split_bf(acc[r]);

    if (tid < 4) {
        float a = b_ssp[i0 + tid];
        for (int j = 0; j < 512; j++) a += s[tid * 512 + j] * b_lin[j];
        g_bc[i0 + tid] = a;
    }
}

// ---------------------------------------------------------------------------
// Kernel 3: recurrence v2. 128 CTAs x 256 threads (8 warps), 16 rows/CTA.
// Warp w owns j-chunk [16w,16w+16); lane = (row-parity, j-offset); each lane
// accumulates 8 rows x 1 output. Extended K: x=[h(128),m'(6),v(2)], 34 k4.
// x rows double-buffered, stride 148 floats (592B: halves hit disjoint banks).
// ---------------------------------------------------------------------------
#define XS 148
__global__ void __launch_bounds__(256) k_recur(
    const float* __restrict__ vel,
    const float* __restrict__ ie_g, const float* __restrict__ he_g,
    const float* __restrict__ me_g, const float* __restrict__ ik_g,
    const float* __restrict__ hk_g, const float* __restrict__ mk_g,
    const float* __restrict__ AT_g, const float* __restrict__ BT_g) {
    extern __shared__ float sm[];
    float* s_wp = sm;                       // [34][128][4]   17408
    float* s_x  = sm + 17408;               // [2][16][148]    4736
    float* s_v  = sm + 17408 + 4736;        // [100][16][2]    3200
    float* s_m  = s_v + 3200;               // [16][8]          128
    float* s_he = s_m + 128;                // [128]
    float* s_c  = s_he + 128;               // AT[36] BT[6] me[6] ie[2]

    const int tid = threadIdx.x;
    const int b0 = blockIdx.x * 16;

    // Extended weight fill: W'[j] = [HK[j][0:128], MK[j][0:6], IK[j][0:2]]
    for (int idx = tid; idx < 34 * 128; idx += 256) {
        const int k4 = idx >> 7, j = idx & 127;
        float p0, p1, p2, p3;
        if (k4 < 32) {
            const float4 h4 = *(const float4*)(hk_g + j * 128 + k4 * 4);
            p0 = h4.x; p1 = h4.y; p2 = h4.z; p3 = h4.w;
        } else if (k4 == 32) {
            p0 = mk_g[j * 6 + 0]; p1 = mk_g[j * 6 + 1];
            p2 = mk_g[j * 6 + 2]; p3 = mk_g[j * 6 + 3];
        } else {
            p0 = mk_g[j * 6 + 4]; p1 = mk_g[j * 6 + 5];
            p2 = ik_g[j * 2 + 0]; p3 = ik_g[j * 2 + 1];
        }
        float4* d = (float4*)(s_wp + (size_t)idx * 4);
        *d = make_float4(p0, p1, p2, p3);
    }
    for (int idx = tid; idx < 16 * 128; idx += 256) {
        const int r = idx >> 7, j = idx & 127;
        s_x[r * XS + j] = g_h0[(size_t)(b0 + r) * NH + j];
    }
    for (int idx = tid; idx < 3200; idx += 256)
        s_v[idx] = vel[(size_t)(idx >> 5) * (BATCH * 2) + b0 * 2 + (idx & 31)];
    for (int idx = tid; idx < 96; idx += 256)
        s_m[(idx / 6) * 8 + (idx % 6)] = g_m0[(size_t)b0 * NORD + idx];
    if (tid < 128) s_he[tid] = he_g[tid];
    if (tid < 36) s_c[tid] = AT_g[tid];
    if (tid < 6) { s_c[36 + tid] = BT_g[tid]; s_c[42 + tid] = me_g[tid]; }
    if (tid < 2) s_c[48 + tid] = ie_g[tid];
    __syncthreads();

    const int lane = tid & 31;
    const int w = tid >> 5;
    const int jj = w * 16 + (lane & 15);  // matvec output column
    const int rh = lane >> 4;             // row parity
    const int r0 = 2 * w, r1 = 2 * w + 1; // phase A/B rows for this warp

    float he4[4];
    #pragma unroll
    for (int q = 0; q < 4; q++) he4[q] = s_he[lane + 32 * q];
    const float ie0 = s_c[48], ie1 = s_c[49];
    float at_row[6], bt_l = 0.f;
    #pragma unroll
    for (int k = 0; k < 6; k++) at_row[k] = (lane < 6) ? s_c[lane * 6 + k] : 0.f;
    if (lane < 6) bt_l = s_c[36 + lane];
    float me6[6];
    #pragma unroll
    for (int o = 0; o < 6; o++) me6[o] = s_c[42 + o];

    #pragma unroll 1
    for (int t = 0; t < T_STEPS; t++) {
        float* xr = s_x + (t & 1) * (16 * XS);
        float* xw = s_x + ((t & 1) ^ 1) * (16 * XS);

        // ---- Phase A: u for rows r0,r1 (old h from xr, old m from s_m) ----
        const float v00 = s_v[t * 32 + r0 * 2],     v01 = s_v[t * 32 + r0 * 2 + 1];
        const float v10 = s_v[t * 32 + r1 * 2],     v11 = s_v[t * 32 + r1 * 2 + 1];
        float ua = 0.f, ub = 0.f;
        #pragma unroll
        for (int q = 0; q < 4; q++) {
            ua += he4[q] * xr[r0 * XS + lane + 32 * q];
            ub += he4[q] * xr[r1 * XS + lane + 32 * q];
        }
        #pragma unroll
        for (int o = 16; o > 0; o >>= 1) {
            ua += __shfl_xor_sync(0xffffffffu, ua, o);
            ub += __shfl_xor_sync(0xffffffffu, ub, o);
        }
        ua += ie0 * v00 + ie1 * v01;
        ub += ie0 * v10 + ie1 * v11;
        #pragma unroll
        for (int o = 0; o < 6; o++) {
            ua += me6[o] * s_m[r0 * 8 + o];
            ub += me6[o] * s_m[r1 * 8 + o];
        }

        // ---- Phase B: m' = m + AT@m + BT*u ; stage m',v into xr ----
        float ma = 0.f, mb = 0.f;
        if (lane < 6) {
            ma = s_m[r0 * 8 + lane] + bt_l * ua;
            mb = s_m[r1 * 8 + lane] + bt_l * ub;
            #pragma unroll
            for (int k = 0; k < 6; k++) {
                ma += at_row[k] * s_m[r0 * 8 + k];
                mb += at_row[k] * s_m[r1 * 8 + k];
            }
        }
        __syncwarp();
        if (lane < 6) {
            s_m[r0 * 8 + lane] = ma;  xr[r0 * XS + 128 + lane] = ma;
            s_m[r1 * 8 + lane] = mb;  xr[r1 * XS + 128 + lane] = mb;
        }
        if (lane == 6) {
            xr[r0 * XS + 134] = v00;  xr[r0 * XS + 135] = v01;
            xr[r1 * XS + 134] = v10;  xr[r1 * XS + 135] = v11;
        }
        __syncthreads();

        // ---- Phase C: extended matvec, 8 rows x 1 j per lane ----
        ull acc[8];
        #pragma unroll
        for (int i = 0; i < 8; i++) acc[i] = 0ull;

        #pragma unroll 2
        for (int k4 = 0; k4 < 34; k4++) {
            const ulonglong2 wp = *(const ulonglong2*)(s_wp + ((size_t)k4 * 128 + jj) * 4);
            #pragma unroll
            for (int i = 0; i < 8; i++) {
                const ulonglong2 hp = *(const ulonglong2*)(xr + (2 * i + rh) * XS + k4 * 4);
                ffma2(acc[i], hp.x, wp.x);
                ffma2(acc[i], hp.y, wp.y);
            }
        }

        #pragma unroll
        for (int i = 0; i < 8; i++) {
            const int row = 2 * i + rh;
            const float x = sum2(acc[i]);
            const float e = __expf(2.f * x);
            const float h = 1.f - __fdividef(2.f, e + 1.f);
            xw[row * XS + jj] = h;
            g_Hp[((size_t)t * BATCH + b0 + row) * NH + jj] = split_bf(h);
        }
        __syncthreads();
    }
}

// ---------------------------------------------------------------------------
// Kernel 4: projection via mma.sync (HMMA) split-bf16, 3 passes, K in 2 halves.
// C[204800,512] = Hsplit @ Wcsplit^T + bc. CTA 128x128, 8 warps, SMEM 64KB
// per stage -> 2 CTAs/SM.
// ---------------------------------------------------------------------------
#define PJ_A_HI 0
#define PJ_A_LO 16384
#define PJ_B_HI 32768
#define PJ_B_LO 49152
#define PJ_SMEM 65536

__device__ __forceinline__ void ldsm4(u32* r, u32 addr) {
    asm volatile("ldmatrix.sync.aligned.m8n8.x4.shared.b16 {%0,%1,%2,%3}, [%4];"
        : "=r"(r[0]), "=r"(r[1]), "=r"(r[2]), "=r"(r[3]) : "r"(addr));
}
__device__ __forceinline__ void mma16816(float* c, const u32* a, const u32* b) {
    asm volatile(
        "mma.sync.aligned.m16n8k16.row.col.f32.bf16.bf16.f32 "
        "{%0,%1,%2,%3}, {%4,%5,%6,%7}, {%8,%9}, {%0,%1,%2,%3};"
        : "+f"(c[0]), "+f"(c[1]), "+f"(c[2]), "+f"(c[3])
        : "r"(a[0]), "r"(a[1]), "r"(a[2]), "r"(a[3]), "r"(b[0]), "r"(b[1]));
}

__global__ void __launch_bounds__(256, 2) k_proj(float* __restrict__ out) {
    extern __shared__ char smc[];
    const u32 sb = smem_u32(smc);
    const int tid = threadIdx.x;
    const int w = tid >> 5, lane = tid & 31;
    const int col0 = blockIdx.x * 128;
    const int row0 = blockIdx.y * 128;

    const int wm = w & 1, wn = w >> 1;
    const int mbase = wm * 64, nbase = wn * 32;
    const int arow_l = lane & 15, asel = lane >> 4;
    const int brow_l = ((lane >> 4) << 3) + (lane & 7), bsel = (lane >> 3) & 1;

    float acc[4][4][4];
    #pragma unroll
    for (int mt = 0; mt < 4; mt++)
        #pragma unroll
        for (int nt = 0; nt < 4; nt++)
            #pragma unroll
            for (int i = 0; i < 4; i++) acc[mt][nt][i] = 0.f;

    const uint4* Ag = (const uint4*)(g_Hp + (size_t)row0 * NH);
    const uint4* Bg = (const uint4*)(g_Wcp + (size_t)col0 * NH);

    #pragma unroll 1
    for (int half = 0; half < 2; half++) {
        if (half) __syncthreads();   // half-0 ldsm complete before overwrite
        for (int idx = tid; idx < 128 * 16; idx += 256) {
            const int row = idx >> 4, c4 = idx & 15;
            const u32 o = (u32)row * 128 + ((u32)(((c4 >> 1) ^ (row & 7)) << 4)) + (c4 & 1) * 8;
            {
                const uint4 v = Ag[row * 32 + half * 16 + c4];
                uint2 hi, lo;
                hi.x = (v.x & 0xffffu) | (v.y << 16);
                hi.y = (v.z & 0xffffu) | (v.w << 16);
                lo.x = (v.x >> 16) | (v.y & 0xffff0000u);
                lo.y = (v.z >> 16) | (v.w & 0xffff0000u);
                *(uint2*)(smc + PJ_A_HI + o) = hi;
                *(uint2*)(smc + PJ_A_LO + o) = lo;
            }
            {
                const uint4 v = Bg[row * 32 + half * 16 + c4];
                uint2 hi, lo;
                hi.x = (v.x & 0xffffu) | (v.y << 16);
                hi.y = (v.z & 0xffffu) | (v.w << 16);
                lo.x = (v.x >> 16) | (v.y & 0xffff0000u);
                lo.y = (v.z >> 16) | (v.w & 0xffff0000u);
                *(uint2*)(smc + PJ_B_HI + o) = hi;
                *(uint2*)(smc + PJ_B_LO + o) = lo;
            }
        }
        __syncthreads();

        #pragma unroll
        for (int kk = 0; kk < 4; kk++) {
            u32 ahi[4][4], alo[4][4];
            #pragma unroll
            for (int mt = 0; mt < 4; mt++) {
                const int row = mbase + mt * 16 + arow_l;
                const u32 off = (u32)row * 128 + ((u32)(((2 * kk + asel) ^ (row & 7)) << 4));
                ldsm4(ahi[mt], sb + PJ_A_HI + off);
                ldsm4(alo[mt], sb + PJ_A_LO + off);
            }
            u32 bhi[2][4], blo[2][4];
            #pragma unroll
            for (int np = 0; np < 2; np++) {
                const int row = nbase + np * 16 + brow_l;
                const u32 off = (u32)row * 128 + ((u32)(((2 * kk + bsel) ^ (row & 7)) << 4));
                ldsm4(bhi[np], sb + PJ_B_HI + off);
                ldsm4(blo[np], sb + PJ_B_LO + off);
            }
            #pragma unroll
            for (int mt = 0; mt < 4; mt++) {
                #pragma unroll
                for (int nt = 0; nt < 4; nt++) {
                    const u32* bh = &bhi[nt >> 1][(nt & 1) * 2];
                    const u32* bl = &blo[nt >> 1][(nt & 1) * 2];
                    mma16816(acc[mt][nt], ahi[mt], bh);   // hi*hi
                    mma16816(acc[mt][nt], alo[mt], bh);   // lo*hi
                    mma16816(acc[mt][nt], ahi[mt], bl);   // hi*lo
                }
            }
        }
    }

    // Epilogue: C-fragment layout -> direct float2 stores + bias
    const int tq = lane >> 2, tr = lane & 3;
    #pragma unroll
    for (int nt = 0; nt < 4; nt++) {
        const int ncol = col0 + nbase + nt * 8 + tr * 2;
        const float2 bias = *(const float2*)(g_bc + ncol);
        #pragma unroll
        for (int mt = 0; mt < 4; mt++) {
            const int mrow = row0 + mbase + mt * 16 + tq;
            float2 v0, v1;
            v0.x = acc[mt][nt][0] + bias.x; v0.y = acc[mt][nt][1] + bias.y;
            v1.x = acc[mt][nt][2] + bias.x; v1.y = acc[mt][nt][3] + bias.y;
            *(float2*)(out + (size_t)mrow * NSP + ncol) = v0;
            *(float2*)(out + (size_t)(mrow + 8) * NSP + ncol) = v1;
        }
    }
}

// ---------------------------------------------------------------------------
extern "C" void kernel_launch(void* const* d_in, const int* in_sizes, int n_in,
                              void* d_out, int out_size) {
    const float* vel   = (const float*)d_in[0];
    const float* ssp0  = (const float*)d_in[1];
    const float* ie    = (const float*)d_in[2];
    const float* he    = (const float*)d_in[3];
    const float* me    = (const float*)d_in[4];
    const float* ik    = (const float*)d_in[5];
    const float* hk    = (const float*)d_in[6];
    const float* mk    = (const float*)d_in[7];
    const float* AT    = (const float*)d_in[8];
    const float* BT    = (const float*)d_in[9];
    const float* w_c   = (const float*)d_in[10];
    const float* w_h   = (const float*)d_in[11];
    const float* W_lin = (const float*)d_in[12];
    const float* b_lin = (const float*)d_in[13];
    const float* W_ssp = (const float*)d_in[14];
    const float* b_ssp = (const float*)d_in[15];
    float* out = (float*)d_out;

    const int recur_smem = (17408 + 4736 + 3200 + 128 + 128 + 64) * 4;
    cudaFuncSetAttribute(k_recur, cudaFuncAttributeMaxDynamicSharedMemorySize, recur_smem);
    cudaFuncSetAttribute(k_proj,  cudaFuncAttributeMaxDynamicSharedMemorySize, PJ_SMEM);

    k_setup<<<128, 128>>>(ssp0, w_c, w_h);
    k_combine<<<128, 128>>>(W_lin, b_lin, W_ssp, b_ssp);
    k_recur<<<128, 256, recur_smem>>>(vel, ie, he, me, ik, hk, mk, AT, BT);
    dim3 g(4, 1600);
    k_proj<<<g, 256, PJ_SMEM>>>(out);
}